// round 3
// baseline (speedup 1.0000x reference)
#include <cuda_runtime.h>

// SOM batch_train: 8192 sequential steps. Persistent 64-CTA kernel,
// warp-per-neuron, register-resident weights, L2-slot spin reduction.
//
// Shapes (fixed for this problem): input [8192,384] f32, weights [32,32,384] f32,
// grid_coordinates [32,32,2] f32 (recomputed on device), num_epochs int (=1).

#define DIM   384
#define KREG  12          // DIM / 32 weight elements per lane
#define NCTA  64
#define NPC   16          // neurons per CTA (1024 / 64)
#define NTHREADS 512      // 16 warps = warp per neuron
#define RING  4

// Inter-CTA reduction slots: packed (d2bits:32 | tag:22 | neuron:10).
// Zero-initialized at load; restored to zero at the end of every launch.
__device__ unsigned long long g_slots[RING][NCTA];

__device__ __forceinline__ unsigned long long ld_acq(const unsigned long long* p) {
    unsigned long long v;
    asm volatile("ld.acquire.gpu.global.b64 %0, [%1];" : "=l"(v) : "l"(p) : "memory");
    return v;
}
__device__ __forceinline__ void st_rel(unsigned long long* p, unsigned long long v) {
    asm volatile("st.release.gpu.global.b64 [%0], %1;" :: "l"(p), "l"(v) : "memory");
}

__global__ void __launch_bounds__(NTHREADS, 1)
som_kernel(const float* __restrict__ X, const float* __restrict__ W0,
           const int* __restrict__ ep, float* __restrict__ out, int n_samples)
{
    const int cta  = blockIdx.x;
    const int warp = threadIdx.x >> 5;
    const int lane = threadIdx.x & 31;
    const int n    = cta * NPC + warp;        // global neuron id, 0..1023
    const int gx   = n >> 5, gy = n & 31;     // grid coords (row-major flatten)

    // Register-resident weights: lane holds dims lane, lane+32, ..., lane+352
    float w[KREG];
#pragma unroll
    for (int k = 0; k < KREG; k++) w[k] = W0[n * DIM + lane + 32 * k];

    int epochs = *ep;
    if (epochs < 1 || epochs > 8) epochs = 1;   // also guards dtype surprises
    const long long TS = (long long)epochs * n_samples;

    __shared__ unsigned long long sm_pack[NPC];
    __shared__ int sm_bmu;

    // Double-buffered sample in registers
    float xa[KREG], xb[KREG];
#pragma unroll
    for (int k = 0; k < KREG; k++) xa[k] = X[lane + 32 * k];

    int sample = 0;
    for (long long t = 0; t < TS; ++t) {
        // ---- prefetch next sample (off critical path) ----
        int nxt = sample + 1; if (nxt == n_samples) nxt = 0;
        const float* xp = X + (size_t)nxt * DIM + lane;
#pragma unroll
        for (int k = 0; k < KREG; k++) xb[k] = xp[32 * k];

        // ---- squared distance to this warp's neuron ----
        float a0 = 0.f, a1 = 0.f, a2 = 0.f, a3 = 0.f;
#pragma unroll
        for (int k = 0; k < KREG; k += 4) {
            float d0 = xa[k + 0] - w[k + 0]; a0 = fmaf(d0, d0, a0);
            float d1 = xa[k + 1] - w[k + 1]; a1 = fmaf(d1, d1, a1);
            float d2v = xa[k + 2] - w[k + 2]; a2 = fmaf(d2v, d2v, a2);
            float d3 = xa[k + 3] - w[k + 3]; a3 = fmaf(d3, d3, a3);
        }
        float d2 = (a0 + a1) + (a2 + a3);
#pragma unroll
        for (int off = 16; off; off >>= 1)
            d2 += __shfl_xor_sync(0xFFFFFFFFu, d2, off);

        const unsigned tag = (unsigned)(t + 1) & 0x3FFFFFu;
        if (lane == 0) {
            unsigned long long pk =
                ((unsigned long long)__float_as_uint(d2) << 32) |
                ((tag << 10) | (unsigned)n);
            sm_pack[warp] = pk;
        }
        __syncthreads();   // bar1: all local packs visible

        if (warp == 0) {
            // ---- CTA-local argmin over 16 neurons (lanes >=16 padded) ----
            unsigned long long p = (lane < NPC) ? sm_pack[lane]
                                                : 0xFFFFFFFFFFFFFFFFull;
            unsigned phi = (unsigned)(p >> 32), plo = (unsigned)p;
            unsigned mhi = __reduce_min_sync(0xFFFFFFFFu, phi);
            unsigned cnd = (phi == mhi) ? plo : 0xFFFFFFFFu;
            unsigned mlo = __reduce_min_sync(0xFFFFFFFFu, cnd);
            unsigned long long cmin = ((unsigned long long)mhi << 32) | mlo;

            const int ring = (int)(t & (RING - 1));
            if (lane == 0) st_rel(&g_slots[ring][cta], cmin);

            // ---- poll all 64 CTA slots (2 per lane) ----
            unsigned long long v0, v1;
            for (;;) {
                v0 = ld_acq(&g_slots[ring][lane]);
                v1 = ld_acq(&g_slots[ring][lane + 32]);
                bool ok = ((((unsigned)v0) >> 10) == tag) &&
                          ((((unsigned)v1) >> 10) == tag);
                if (__all_sync(0xFFFFFFFFu, ok)) break;
            }
            unsigned long long vm = (v0 < v1) ? v0 : v1;
            unsigned qhi = (unsigned)(vm >> 32), qlo = (unsigned)vm;
            unsigned gh = __reduce_min_sync(0xFFFFFFFFu, qhi);
            unsigned gc = (qhi == gh) ? qlo : 0xFFFFFFFFu;
            unsigned gl = __reduce_min_sync(0xFFFFFFFFu, gc);
            if (lane == 0) sm_bmu = (int)(gl & 0x3FFu);
        }
        __syncthreads();   // bar2: bmu visible to all warps

        // ---- neighborhood update: c = LR * exp(-dist/(2*sigma^2)), dist NOT squared ----
        const int bmu = sm_bmu;
        const float dx = (float)(gx - (bmu >> 5));
        const float dy = (float)(gy - (bmu & 31));
        const float dist = sqrtf(dx * dx + dy * dy);
        const float c = 0.1f * __expf(-0.5f * dist);

#pragma unroll
        for (int k = 0; k < KREG; k++) {
            w[k] = fmaf(c, xa[k] - w[k], w[k]);
            xa[k] = xb[k];
        }
        sample = nxt;
    }

    // ---- write final weights ----
#pragma unroll
    for (int k = 0; k < KREG; k++) out[n * DIM + lane + 32 * k] = w[k];

    // ---- termination handshake + scratch cleanup (deterministic replays) ----
    const unsigned ftag = (unsigned)(TS + 1) & 0x3FFFFFu;
    const int fring = (int)(TS & (RING - 1));
    if (warp == 0 && lane == 0)
        st_rel(&g_slots[fring][cta], (unsigned long long)(ftag << 10));

    if (cta == 0 && warp == 0) {
        for (;;) {
            unsigned long long v0 = ld_acq(&g_slots[fring][lane]);
            unsigned long long v1 = ld_acq(&g_slots[fring][lane + 32]);
            bool ok = ((((unsigned)v0) >> 10) == ftag) &&
                      ((((unsigned)v1) >> 10) == ftag);
            if (__all_sync(0xFFFFFFFFu, ok)) break;
        }
        // Every CTA has finished all reads: zero the ring for the next launch.
#pragma unroll
        for (int r = 0; r < RING; r++) {
            g_slots[r][lane] = 0ull;
            g_slots[r][lane + 32] = 0ull;
        }
        __threadfence();
    }
}

extern "C" void kernel_launch(void* const* d_in, const int* in_sizes, int n_in,
                              void* d_out, int out_size)
{
    const float* X  = (const float*)d_in[0];   // [8192, 384]
    const float* W0 = (const float*)d_in[1];   // [32, 32, 384]
    const int*   ep = (const int*)d_in[3];     // num_epochs
    float* out = (float*)d_out;                // [32, 32, 384]

    int n_samples = in_sizes[0] / DIM;
    som_kernel<<<NCTA, NTHREADS>>>(X, W0, ep, out, n_samples);
}

// round 4
// speedup vs baseline: 1.0512x; 1.0512x over previous
#include <cuda_runtime.h>

// SOM batch_train: 8192 sequential steps. Persistent 64-CTA kernel,
// warp-per-neuron, register-resident weights, L2-slot spin reduction.
//
// Shapes (fixed for this problem): input [8192,384] f32, weights [32,32,384] f32,
// grid_coordinates [32,32,2] f32 (recomputed on device), num_epochs int (=1).

#define DIM   384
#define KREG  12          // DIM / 32 weight elements per lane
#define NCTA  64
#define NPC   16          // neurons per CTA (1024 / 64)
#define NTHREADS 512      // 16 warps = warp per neuron
#define RING  4

// Inter-CTA reduction slots: packed (d2bits:32 | tag:22 | neuron:10).
// Zero-initialized at load; restored to zero at the end of every launch.
__device__ unsigned long long g_slots[RING][NCTA];

__device__ __forceinline__ unsigned long long ld_acq(const unsigned long long* p) {
    unsigned long long v;
    asm volatile("ld.acquire.gpu.global.b64 %0, [%1];" : "=l"(v) : "l"(p) : "memory");
    return v;
}
__device__ __forceinline__ void st_rel(unsigned long long* p, unsigned long long v) {
    asm volatile("st.release.gpu.global.b64 [%0], %1;" :: "l"(p), "l"(v) : "memory");
}

__global__ void __launch_bounds__(NTHREADS, 1)
som_kernel(const float* __restrict__ X, const float* __restrict__ W0,
           const int* __restrict__ ep, float* __restrict__ out, int n_samples)
{
    const int cta  = blockIdx.x;
    const int warp = threadIdx.x >> 5;
    const int lane = threadIdx.x & 31;
    const int n    = cta * NPC + warp;        // global neuron id, 0..1023
    const int gx   = n >> 5, gy = n & 31;     // grid coords (row-major flatten)

    // Register-resident weights: lane holds dims lane, lane+32, ..., lane+352
    float w[KREG];
#pragma unroll
    for (int k = 0; k < KREG; k++) w[k] = W0[n * DIM + lane + 32 * k];

    int epochs = *ep;
    if (epochs < 1 || epochs > 8) epochs = 1;   // also guards dtype surprises
    const long long TS = (long long)epochs * n_samples;

    __shared__ unsigned long long sm_pack[NPC];
    __shared__ int sm_bmu;

    // Double-buffered sample in registers
    float xa[KREG], xb[KREG];
#pragma unroll
    for (int k = 0; k < KREG; k++) xa[k] = X[lane + 32 * k];

    int sample = 0;
    for (long long t = 0; t < TS; ++t) {
        // ---- prefetch next sample (off critical path) ----
        int nxt = sample + 1; if (nxt == n_samples) nxt = 0;
        const float* xp = X + (size_t)nxt * DIM + lane;
#pragma unroll
        for (int k = 0; k < KREG; k++) xb[k] = xp[32 * k];

        // ---- squared distance to this warp's neuron ----
        float a0 = 0.f, a1 = 0.f, a2 = 0.f, a3 = 0.f;
#pragma unroll
        for (int k = 0; k < KREG; k += 4) {
            float d0 = xa[k + 0] - w[k + 0]; a0 = fmaf(d0, d0, a0);
            float d1 = xa[k + 1] - w[k + 1]; a1 = fmaf(d1, d1, a1);
            float d2v = xa[k + 2] - w[k + 2]; a2 = fmaf(d2v, d2v, a2);
            float d3 = xa[k + 3] - w[k + 3]; a3 = fmaf(d3, d3, a3);
        }
        float d2 = (a0 + a1) + (a2 + a3);
#pragma unroll
        for (int off = 16; off; off >>= 1)
            d2 += __shfl_xor_sync(0xFFFFFFFFu, d2, off);

        const unsigned tag = (unsigned)(t + 1) & 0x3FFFFFu;
        if (lane == 0) {
            unsigned long long pk =
                ((unsigned long long)__float_as_uint(d2) << 32) |
                ((tag << 10) | (unsigned)n);
            sm_pack[warp] = pk;
        }
        __syncthreads();   // bar1: all local packs visible

        if (warp == 0) {
            // ---- CTA-local argmin over 16 neurons (lanes >=16 padded) ----
            unsigned long long p = (lane < NPC) ? sm_pack[lane]
                                                : 0xFFFFFFFFFFFFFFFFull;
            unsigned phi = (unsigned)(p >> 32), plo = (unsigned)p;
            unsigned mhi = __reduce_min_sync(0xFFFFFFFFu, phi);
            unsigned cnd = (phi == mhi) ? plo : 0xFFFFFFFFu;
            unsigned mlo = __reduce_min_sync(0xFFFFFFFFu, cnd);
            unsigned long long cmin = ((unsigned long long)mhi << 32) | mlo;

            const int ring = (int)(t & (RING - 1));
            if (lane == 0) st_rel(&g_slots[ring][cta], cmin);

            // ---- poll all 64 CTA slots (2 per lane) ----
            unsigned long long v0, v1;
            for (;;) {
                v0 = ld_acq(&g_slots[ring][lane]);
                v1 = ld_acq(&g_slots[ring][lane + 32]);
                bool ok = ((((unsigned)v0) >> 10) == tag) &&
                          ((((unsigned)v1) >> 10) == tag);
                if (__all_sync(0xFFFFFFFFu, ok)) break;
            }
            unsigned long long vm = (v0 < v1) ? v0 : v1;
            unsigned qhi = (unsigned)(vm >> 32), qlo = (unsigned)vm;
            unsigned gh = __reduce_min_sync(0xFFFFFFFFu, qhi);
            unsigned gc = (qhi == gh) ? qlo : 0xFFFFFFFFu;
            unsigned gl = __reduce_min_sync(0xFFFFFFFFu, gc);
            if (lane == 0) sm_bmu = (int)(gl & 0x3FFu);
        }
        __syncthreads();   // bar2: bmu visible to all warps

        // ---- neighborhood update: c = LR * exp(-dist/(2*sigma^2)), dist NOT squared ----
        const int bmu = sm_bmu;
        const float dx = (float)(gx - (bmu >> 5));
        const float dy = (float)(gy - (bmu & 31));
        const float dist = sqrtf(dx * dx + dy * dy);
        const float c = 0.1f * __expf(-0.5f * dist);

#pragma unroll
        for (int k = 0; k < KREG; k++) {
            w[k] = fmaf(c, xa[k] - w[k], w[k]);
            xa[k] = xb[k];
        }
        sample = nxt;
    }

    // ---- write final weights ----
#pragma unroll
    for (int k = 0; k < KREG; k++) out[n * DIM + lane + 32 * k] = w[k];

    // ---- termination handshake + scratch cleanup (deterministic replays) ----
    const unsigned ftag = (unsigned)(TS + 1) & 0x3FFFFFu;
    const int fring = (int)(TS & (RING - 1));
    if (warp == 0 && lane == 0)
        st_rel(&g_slots[fring][cta], (unsigned long long)(ftag << 10));

    if (cta == 0 && warp == 0) {
        for (;;) {
            unsigned long long v0 = ld_acq(&g_slots[fring][lane]);
            unsigned long long v1 = ld_acq(&g_slots[fring][lane + 32]);
            bool ok = ((((unsigned)v0) >> 10) == ftag) &&
                      ((((unsigned)v1) >> 10) == ftag);
            if (__all_sync(0xFFFFFFFFu, ok)) break;
        }
        // Every CTA has finished all reads: zero the ring for the next launch.
#pragma unroll
        for (int r = 0; r < RING; r++) {
            g_slots[r][lane] = 0ull;
            g_slots[r][lane + 32] = 0ull;
        }
        __threadfence();
    }
}

extern "C" void kernel_launch(void* const* d_in, const int* in_sizes, int n_in,
                              void* d_out, int out_size)
{
    const float* X  = (const float*)d_in[0];   // [8192, 384]
    const float* W0 = (const float*)d_in[1];   // [32, 32, 384]
    const int*   ep = (const int*)d_in[3];     // num_epochs
    float* out = (float*)d_out;                // [32, 32, 384]

    int n_samples = in_sizes[0] / DIM;
    som_kernel<<<NCTA, NTHREADS>>>(X, W0, ep, out, n_samples);
}

// round 9
// speedup vs baseline: 2.6946x; 2.5633x over previous
#include <cuda_runtime.h>

// SOM batch_train, 8192 inherently-sequential steps.
// Persistent 64-CTA kernel: 16 neuron warps + 1 comm warp per CTA (544 thr),
// register-resident weights, L2-slot spin reduction, convergent __syncthreads.
//
// R9 delta vs R8 (hung): poll uses RELAXED ATOMICS (ld/st.relaxed.gpu) instead
// of weak .cg ops. Weak ops racing on one location are UB in the PTX memory
// model (no visibility guarantee -> suspected hang); relaxed atomics are
// morally strong (guaranteed visibility) with zero ordering cost, so the two
// poll loads per iteration still overlap. Payload+tag share one aligned 8-byte
// word, so single-copy atomicity alone gives consistency.
//
// d2 recurrence (drift-free): with u = x_{t+1}-w_t, v = x_t-w_t,
//   d2_{t+1} = A - 2cB + c^2 V,  A=|u|^2, B=<u,v>, V=|v|^2  (all fresh sums)
// A,B,V + weight update + prefetch are BMU-independent -> hidden under poll.

#define DIM      384
#define KREG     12           // DIM / 32 dims per lane
#define NCTA     64
#define NPC      16           // neurons per CTA
#define NTHREADS 544          // 16 neuron warps + 1 comm warp
#define RING     4
#define SLOT_STRIDE 16        // u64 per slot -> one 128B line per CTA slot

// packed (d2bits:32 | tag:22 | neuron:10); zero at load, re-zeroed each launch
__device__ unsigned long long g_slots[RING][NCTA * SLOT_STRIDE];

static __device__ __forceinline__ unsigned long long ld_rlx(const unsigned long long* p) {
    unsigned long long v;
    asm volatile("ld.relaxed.gpu.global.b64 %0, [%1];" : "=l"(v) : "l"(p) : "memory");
    return v;
}
static __device__ __forceinline__ void st_rlx(unsigned long long* p, unsigned long long v) {
    asm volatile("st.relaxed.gpu.global.b64 [%0], %1;" :: "l"(p), "l"(v) : "memory");
}

__global__ void __launch_bounds__(NTHREADS, 1)
som_kernel(const float* __restrict__ X, const float* __restrict__ W0,
           const int* __restrict__ ep, float* __restrict__ out, int n_samples)
{
    const int cta  = blockIdx.x;
    const int tid  = threadIdx.x;
    const int warp = tid >> 5;
    const int lane = tid & 31;

    int epochs = *ep;
    if (epochs < 1 || epochs > 8) epochs = 1;
    const int TS = epochs * n_samples;           // <= 65536, tags fit 22 bits

    __shared__ float c_table[63 * 63];           // 0.1*exp(-0.5*sqrt(dx^2+dy^2))
    __shared__ unsigned long long sm_pack[NPC];
    __shared__ int sm_bmu;

    // ---- neighborhood coefficient LUT (all threads; read after iter-0 syncs) ----
    for (int i = tid; i < 63 * 63; i += NTHREADS) {
        float dx = (float)(i / 63 - 31);
        float dy = (float)(i % 63 - 31);
        c_table[i] = 0.1f * expf(-0.5f * sqrtf(dx * dx + dy * dy));
    }

    // ---- neuron-warp state (comm warp leaves these unused) ----
    const int n  = cta * NPC + warp;             // valid for warp < 16
    const int gx = n >> 5, gy = n & 31;
    float w[KREG], v[KREG], u[KREG], xn[KREG];
    float cp = 0.f;                              // c_{t-1}
    int pf = (n_samples > 2) ? 2 : (2 % n_samples);

    if (warp < NPC) {
        float a0 = 0.f, a1 = 0.f, a2 = 0.f, a3 = 0.f;
#pragma unroll
        for (int k = 0; k < KREG; k++) {
            float wk = W0[n * DIM + lane + 32 * k];
            w[k] = wk;
            v[k] = 0.f;
            float t0 = X[lane + 32 * k] - wk;    // u = x0 - w0
            u[k] = t0;
            if ((k & 3) == 0) a0 = fmaf(t0, t0, a0);
            else if ((k & 3) == 1) a1 = fmaf(t0, t0, a1);
            else if ((k & 3) == 2) a2 = fmaf(t0, t0, a2);
            else a3 = fmaf(t0, t0, a3);
        }
        float d2 = (a0 + a1) + (a2 + a3);
#pragma unroll
        for (int off = 16; off; off >>= 1)
            d2 += __shfl_xor_sync(0xFFFFFFFFu, d2, off);
#pragma unroll
        for (int k = 0; k < KREG; k++) xn[k] = X[DIM + lane + 32 * k];   // x1

        if (lane == 0)
            sm_pack[warp] = ((unsigned long long)__float_as_uint(d2) << 32)
                          | ((1u << 10) | (unsigned)n);
    }

    for (int t = 0; t < TS; ++t) {
        __syncthreads();                          // syncA: pack(t) visible

        float A = 0.f, B = 0.f, V = 0.f;
        if (warp == NPC) {
            // ================= comm warp =================
            const unsigned tag = (unsigned)(t + 1) & 0x3FFFFFu;
            unsigned long long p = (lane < NPC) ? sm_pack[lane]
                                                : 0xFFFFFFFFFFFFFFFFull;
            unsigned phi = (unsigned)(p >> 32), plo = (unsigned)p;
            unsigned mhi = __reduce_min_sync(0xFFFFFFFFu, phi);
            unsigned cnd = (phi == mhi) ? plo : 0xFFFFFFFFu;
            unsigned mlo = __reduce_min_sync(0xFFFFFFFFu, cnd);

            const int ring = t & (RING - 1);
            if (lane == 0)
                st_rlx(&g_slots[ring][cta * SLOT_STRIDE],
                       ((unsigned long long)mhi << 32) | mlo);

            // relaxed-atomic poll: tag+payload in one 8B word, both loads overlap
            unsigned long long v0, v1;
            for (;;) {
                v0 = ld_rlx(&g_slots[ring][lane * SLOT_STRIDE]);
                v1 = ld_rlx(&g_slots[ring][(lane + 32) * SLOT_STRIDE]);
                bool ok = ((((unsigned)v0) >> 10) == tag) &&
                          ((((unsigned)v1) >> 10) == tag);
                if (__all_sync(0xFFFFFFFFu, ok)) break;
            }
            unsigned long long vm = (v0 < v1) ? v0 : v1;
            unsigned qhi = (unsigned)(vm >> 32), qlo = (unsigned)vm;
            unsigned gh = __reduce_min_sync(0xFFFFFFFFu, qhi);
            unsigned gc = (qhi == gh) ? qlo : 0xFFFFFFFFu;
            unsigned gl = __reduce_min_sync(0xFFFFFFFFu, gc);
            if (lane == 0) sm_bmu = (int)(gl & 0x3FFu);
        } else {
            // ====== neuron window work (hidden under the poll) ======
            // w_t = w + cp*v ; v_t = u - cp*v ; u_t = xn - w_t
#pragma unroll
            for (int k = 0; k < KREG; k++) {
                float vo = v[k];
                w[k] = fmaf(cp, vo, w[k]);
                v[k] = fmaf(-cp, vo, u[k]);
                u[k] = xn[k] - w[k];
            }
            // prefetch x_{t+2} (consumed next window)
            const float* xp = X + (size_t)pf * DIM + lane;
#pragma unroll
            for (int k = 0; k < KREG; k++) xn[k] = xp[32 * k];
            pf++; if (pf == n_samples) pf = 0;

            float a0 = 0.f, a1 = 0.f, b0 = 0.f, b1 = 0.f, v0 = 0.f, v1 = 0.f;
#pragma unroll
            for (int k = 0; k < KREG; k += 2) {
                a0 = fmaf(u[k + 0], u[k + 0], a0); b0 = fmaf(u[k + 0], v[k + 0], b0);
                v0 = fmaf(v[k + 0], v[k + 0], v0);
                a1 = fmaf(u[k + 1], u[k + 1], a1); b1 = fmaf(u[k + 1], v[k + 1], b1);
                v1 = fmaf(v[k + 1], v[k + 1], v1);
            }
            A = a0 + a1; B = b0 + b1; V = v0 + v1;
#pragma unroll
            for (int off = 16; off; off >>= 1) {
                A += __shfl_xor_sync(0xFFFFFFFFu, A, off);
                B += __shfl_xor_sync(0xFFFFFFFFu, B, off);
                V += __shfl_xor_sync(0xFFFFFFFFu, V, off);
            }
        }

        __syncthreads();                          // syncB: bmu visible

        if (warp < NPC) {
            // ---- critical tail: LUT lookup + 2 FMA + publish ----
            const int bmu = sm_bmu;
            const float c = c_table[(gx - (bmu >> 5) + 31) * 63
                                  + (gy - (bmu & 31) + 31)];
            // clamp: |u-cv|^2 can round negative; negative float bits would
            // compare as huge unsigned and corrupt the argmin
            float d2 = fmaxf(fmaf(c, fmaf(c, V, -2.f * B), A), 0.f);
            cp = c;
            if (lane == 0) {
                unsigned tag = (unsigned)(t + 2) & 0x3FFFFFu;
                sm_pack[warp] = ((unsigned long long)__float_as_uint(d2) << 32)
                              | ((tag << 10) | (unsigned)n);
            }
        }
    }

    if (warp < NPC) {
        // epilogue: apply last update, write final weights
#pragma unroll
        for (int k = 0; k < KREG; k++)
            out[n * DIM + lane + 32 * k] = fmaf(cp, v[k], w[k]);
    } else {
        // ---- termination handshake + scratch cleanup (deterministic replays) ----
        const unsigned ftag = (unsigned)(TS + 1) & 0x3FFFFFu;
        const int fring = TS & (RING - 1);
        if (lane == 0)
            st_rlx(&g_slots[fring][cta * SLOT_STRIDE],
                   (unsigned long long)(ftag << 10));

        if (cta == 0) {
            for (;;) {
                unsigned long long v0 = ld_rlx(&g_slots[fring][lane * SLOT_STRIDE]);
                unsigned long long v1 = ld_rlx(&g_slots[fring][(lane + 32) * SLOT_STRIDE]);
                bool ok = ((((unsigned)v0) >> 10) == ftag) &&
                          ((((unsigned)v1) >> 10) == ftag);
                if (__all_sync(0xFFFFFFFFu, ok)) break;
            }
            // every CTA's final store observed: zero the ring for next launch
#pragma unroll
            for (int r = 0; r < RING; r++) {
                st_rlx(&g_slots[r][lane * SLOT_STRIDE], 0ull);
                st_rlx(&g_slots[r][(lane + 32) * SLOT_STRIDE], 0ull);
            }
            __threadfence();
        }
    }
}

extern "C" void kernel_launch(void* const* d_in, const int* in_sizes, int n_in,
                              void* d_out, int out_size)
{
    const float* X  = (const float*)d_in[0];   // [8192, 384]
    const float* W0 = (const float*)d_in[1];   // [32, 32, 384]
    const int*   ep = (const int*)d_in[3];     // num_epochs
    float* out = (float*)d_out;                // [32, 32, 384]

    int n_samples = in_sizes[0] / DIM;
    som_kernel<<<NCTA, NTHREADS>>>(X, W0, ep, out, n_samples);
}

// round 10
// speedup vs baseline: 3.0394x; 1.1280x over previous
#include <cuda_runtime.h>

// SOM batch_train, 8192 inherently-sequential steps.
// Persistent 64-CTA kernel: 16 neuron warps + 1 comm warp per CTA (544 thr).
// R10 delta vs R9 (9406us): the post-BMU tail (c lookup, d2 recurrence, pack,
// CTA argmin, slot store) moves INTO the comm warp, using per-neuron (A,B,V)
// scalars deposited by neuron warps during the poll shadow. Critical path per
// step: poll detect -> global redux -> LUT c -> one syncthreads -> smem ABV ->
// 2 FMA -> 2 REDUX -> st.relaxed. Neuron warps leave the critical path.
//
//   d2_{t+1} = A - 2cB + c^2 V,  u=x_{t+1}-w_t, v=x_t-w_t, A=|u|^2,B=<u,v>,V=|v|^2
// All sums fresh each step (no drift). sm_c/sm_ABV double-buffered by parity.

#define DIM      384
#define KREG     12           // DIM / 32 dims per lane
#define NCTA     64
#define NPC      16           // neurons per CTA
#define NTHREADS 544          // 16 neuron warps + 1 comm warp
#define RING     4
#define SLOT_STRIDE 16        // u64 per slot -> one 128B line per CTA slot

// packed (d2bits:32 | tag:22 | neuron:10); zero at load, re-zeroed each launch
__device__ unsigned long long g_slots[RING][NCTA * SLOT_STRIDE];

static __device__ __forceinline__ unsigned long long ld_rlx(const unsigned long long* p) {
    unsigned long long v;
    asm volatile("ld.relaxed.gpu.global.b64 %0, [%1];" : "=l"(v) : "l"(p) : "memory");
    return v;
}
static __device__ __forceinline__ void st_rlx(unsigned long long* p, unsigned long long v) {
    asm volatile("st.relaxed.gpu.global.b64 [%0], %1;" :: "l"(p), "l"(v) : "memory");
}

__global__ void __launch_bounds__(NTHREADS, 1)
som_kernel(const float* __restrict__ X, const float* __restrict__ W0,
           const int* __restrict__ ep, float* __restrict__ out, int n_samples)
{
    const int cta  = blockIdx.x;
    const int tid  = threadIdx.x;
    const int warp = tid >> 5;
    const int lane = tid & 31;

    int epochs = *ep;
    if (epochs < 1 || epochs > 8) epochs = 1;
    const int TS = epochs * n_samples;           // <= 65536, tags fit 22 bits

    __shared__ float c_table[63 * 63];           // 0.1*exp(-0.5*sqrt(dx^2+dy^2))
    __shared__ float sm_A[2][NPC], sm_B[2][NPC], sm_V[2][NPC];  // parity-buffered
    __shared__ float sm_c[2][NPC];               // per-neuron c, parity-buffered
    __shared__ unsigned long long sm_pack[NPC];  // prologue only

    for (int i = tid; i < 63 * 63; i += NTHREADS) {
        float dx = (float)(i / 63 - 31);
        float dy = (float)(i % 63 - 31);
        c_table[i] = 0.1f * expf(-0.5f * sqrtf(dx * dx + dy * dy));
    }
    if (tid < NPC) sm_c[1][tid] = 0.f;           // c(-1) = 0 for iteration 0

    // ---- neuron-warp state ----
    const int n = cta * NPC + warp;              // valid for warp < 16
    float w[KREG], v[KREG], u[KREG], xn[KREG];
    int pf = (n_samples > 2) ? 2 : (2 % n_samples);

    if (warp < NPC) {
        float a0 = 0.f, a1 = 0.f, a2 = 0.f, a3 = 0.f;
#pragma unroll
        for (int k = 0; k < KREG; k++) {
            float wk = W0[n * DIM + lane + 32 * k];
            w[k] = wk;
            v[k] = 0.f;
            float t0 = X[lane + 32 * k] - wk;    // u = x0 - w0
            u[k] = t0;
            if ((k & 3) == 0) a0 = fmaf(t0, t0, a0);
            else if ((k & 3) == 1) a1 = fmaf(t0, t0, a1);
            else if ((k & 3) == 2) a2 = fmaf(t0, t0, a2);
            else a3 = fmaf(t0, t0, a3);
        }
        float d2 = (a0 + a1) + (a2 + a3);
#pragma unroll
        for (int off = 16; off; off >>= 1)
            d2 += __shfl_xor_sync(0xFFFFFFFFu, d2, off);
#pragma unroll
        for (int k = 0; k < KREG; k++) xn[k] = X[DIM + lane + 32 * k];   // x1

        if (lane == 0)
            sm_pack[warp] = ((unsigned long long)__float_as_uint(d2) << 32)
                          | ((1u << 10) | (unsigned)n);
    }

    __syncthreads();                             // packs + sm_c[1] + LUT visible

    if (warp == NPC) {                           // store candidate(0), tag 1
        unsigned long long p = (lane < NPC) ? sm_pack[lane] : 0xFFFFFFFFFFFFFFFFull;
        unsigned phi = (unsigned)(p >> 32), plo = (unsigned)p;
        unsigned mhi = __reduce_min_sync(0xFFFFFFFFu, phi);
        unsigned cnd = (phi == mhi) ? plo : 0xFFFFFFFFu;
        unsigned mlo = __reduce_min_sync(0xFFFFFFFFu, cnd);
        if (lane == 0)
            st_rlx(&g_slots[0][cta * SLOT_STRIDE],
                   ((unsigned long long)mhi << 32) | mlo);
    }

    float ci = 0.f;                              // comm-lane c (persists across sync)
    const int nl = cta * NPC + (lane & 15);      // comm-lane neuron id (in range)
    const int ngx = nl >> 5, ngy = nl & 31;

    for (int t = 0; t < TS; ++t) {
        const int par = t & 1;

        if (warp == NPC) {
            // ======== comm: poll bmu(t), compute per-neuron c ========
            const unsigned tag = (unsigned)(t + 1) & 0x3FFFFFu;
            const int ring = t & (RING - 1);
            unsigned long long v0, v1;
            for (;;) {
                v0 = ld_rlx(&g_slots[ring][lane * SLOT_STRIDE]);
                v1 = ld_rlx(&g_slots[ring][(lane + 32) * SLOT_STRIDE]);
                bool ok = ((((unsigned)v0) >> 10) == tag) &&
                          ((((unsigned)v1) >> 10) == tag);
                if (__all_sync(0xFFFFFFFFu, ok)) break;
            }
            unsigned long long vm = (v0 < v1) ? v0 : v1;
            unsigned qhi = (unsigned)(vm >> 32), qlo = (unsigned)vm;
            unsigned gh = __reduce_min_sync(0xFFFFFFFFu, qhi);
            unsigned gc = (qhi == gh) ? qlo : 0xFFFFFFFFu;
            unsigned gl = __reduce_min_sync(0xFFFFFFFFu, gc);
            const int bmu = (int)(gl & 0x3FFu);

            ci = c_table[(ngx - (bmu >> 5) + 31) * 63 + (ngy - (bmu & 31) + 31)];
            if (lane < NPC) sm_c[par][lane] = ci;    // consumed at iter t+1
        } else {
            // ======== neurons: window work (poll shadow) ========
            const float cp = sm_c[par ^ 1][warp];    // c(t-1), written iter t-1
#pragma unroll
            for (int k = 0; k < KREG; k++) {
                float vo = v[k];
                w[k] = fmaf(cp, vo, w[k]);
                v[k] = fmaf(-cp, vo, u[k]);
                u[k] = xn[k] - w[k];
            }
            const float* xp = X + (size_t)pf * DIM + lane;   // prefetch x(t+2)
#pragma unroll
            for (int k = 0; k < KREG; k++) xn[k] = xp[32 * k];
            pf++; if (pf == n_samples) pf = 0;

            float a0 = 0.f, a1 = 0.f, b0 = 0.f, b1 = 0.f, q0 = 0.f, q1 = 0.f;
#pragma unroll
            for (int k = 0; k < KREG; k += 2) {
                a0 = fmaf(u[k + 0], u[k + 0], a0); b0 = fmaf(u[k + 0], v[k + 0], b0);
                q0 = fmaf(v[k + 0], v[k + 0], q0);
                a1 = fmaf(u[k + 1], u[k + 1], a1); b1 = fmaf(u[k + 1], v[k + 1], b1);
                q1 = fmaf(v[k + 1], v[k + 1], q1);
            }
            float A = a0 + a1, B = b0 + b1, V = q0 + q1;
#pragma unroll
            for (int off = 16; off; off >>= 1) {
                A += __shfl_xor_sync(0xFFFFFFFFu, A, off);
                B += __shfl_xor_sync(0xFFFFFFFFu, B, off);
                V += __shfl_xor_sync(0xFFFFFFFFu, V, off);
            }
            if (lane == 0) {
                sm_A[par][warp] = A; sm_B[par][warp] = B; sm_V[par][warp] = V;
            }
        }

        __syncthreads();   // joins: bmu/c(t) + ABV(t) visible (neurons arrived early)

        if (warp == NPC && t + 1 < TS) {
            // ======== comm tail: d2(t+1), CTA argmin, publish ========
            float A = sm_A[par][lane & 15];
            float B = sm_B[par][lane & 15];
            float V = sm_V[par][lane & 15];
            float d2 = fmaxf(fmaf(ci, fmaf(ci, V, -2.f * B), A), 0.f);
            unsigned tag2 = (unsigned)(t + 2) & 0x3FFFFFu;
            unsigned long long pk = (lane < NPC)
                ? (((unsigned long long)__float_as_uint(d2) << 32)
                   | ((tag2 << 10) | (unsigned)nl))
                : 0xFFFFFFFFFFFFFFFFull;
            unsigned phi = (unsigned)(pk >> 32), plo = (unsigned)pk;
            unsigned mhi = __reduce_min_sync(0xFFFFFFFFu, phi);
            unsigned cnd = (phi == mhi) ? plo : 0xFFFFFFFFu;
            unsigned mlo = __reduce_min_sync(0xFFFFFFFFu, cnd);
            if (lane == 0)
                st_rlx(&g_slots[(t + 1) & (RING - 1)][cta * SLOT_STRIDE],
                       ((unsigned long long)mhi << 32) | mlo);
        }
    }

    if (warp < NPC) {
        // epilogue: apply final update c(TS-1), write weights
        const float cp = sm_c[(TS - 1) & 1][warp];
#pragma unroll
        for (int k = 0; k < KREG; k++)
            out[n * DIM + lane + 32 * k] = fmaf(cp, v[k], w[k]);
    } else {
        // ---- termination handshake + scratch cleanup (deterministic replays) ----
        // ring(TS&3) received no candidate store (skipped at t=TS-1), so the
        // handshake tag TS+1 is this slot's unique terminal value.
        const unsigned ftag = (unsigned)(TS + 1) & 0x3FFFFFu;
        const int fring = TS & (RING - 1);
        if (lane == 0)
            st_rlx(&g_slots[fring][cta * SLOT_STRIDE],
                   (unsigned long long)(ftag << 10));

        if (cta == 0) {
            for (;;) {
                unsigned long long v0 = ld_rlx(&g_slots[fring][lane * SLOT_STRIDE]);
                unsigned long long v1 = ld_rlx(&g_slots[fring][(lane + 32) * SLOT_STRIDE]);
                bool ok = ((((unsigned)v0) >> 10) == ftag) &&
                          ((((unsigned)v1) >> 10) == ftag);
                if (__all_sync(0xFFFFFFFFu, ok)) break;
            }
#pragma unroll
            for (int r = 0; r < RING; r++) {
                st_rlx(&g_slots[r][lane * SLOT_STRIDE], 0ull);
                st_rlx(&g_slots[r][(lane + 32) * SLOT_STRIDE], 0ull);
            }
            __threadfence();
        }
    }
}

extern "C" void kernel_launch(void* const* d_in, const int* in_sizes, int n_in,
                              void* d_out, int out_size)
{
    const float* X  = (const float*)d_in[0];   // [8192, 384]
    const float* W0 = (const float*)d_in[1];   // [32, 32, 384]
    const int*   ep = (const int*)d_in[3];     // num_epochs
    float* out = (float*)d_out;                // [32, 32, 384]

    int n_samples = in_sizes[0] / DIM;
    som_kernel<<<NCTA, NTHREADS>>>(X, W0, ep, out, n_samples);
}

// round 11
// speedup vs baseline: 3.0850x; 1.0150x over previous
#include <cuda_runtime.h>

// SOM batch_train, 8192 inherently-sequential steps.
// Persistent 64-CTA kernel: 16 neuron warps + 1 comm warp per CTA (544 thr).
// R11 delta vs R10 (8339us): (1) pipelined poll -- two independent load pairs
// in flight per loop body halve detect quantization; (2) ABV handoff as one
// float4 (A, -2B, V) -> single LDS/STS.128 and the -2*B multiply off the tail;
// (3) tail micro-scheduling. Protocol (relaxed atomics, ring, two syncs,
// handshake) unchanged from R10.
//
//   d2_{t+1} = A - 2cB + c^2 V,  u=x_{t+1}-w_t, v=x_t-w_t, A=|u|^2,B=<u,v>,V=|v|^2
// All sums fresh each step (no drift). sm_c/sm_ABV double-buffered by parity.

#define DIM      384
#define KREG     12           // DIM / 32 dims per lane
#define NCTA     64
#define NPC      16           // neurons per CTA
#define NTHREADS 544          // 16 neuron warps + 1 comm warp
#define RING     4
#define SLOT_STRIDE 16        // u64 per slot -> one 128B line per CTA slot

// packed (d2bits:32 | tag:22 | neuron:10); zero at load, re-zeroed each launch
__device__ unsigned long long g_slots[RING][NCTA * SLOT_STRIDE];

static __device__ __forceinline__ unsigned long long ld_rlx(const unsigned long long* p) {
    unsigned long long v;
    asm volatile("ld.relaxed.gpu.global.b64 %0, [%1];" : "=l"(v) : "l"(p) : "memory");
    return v;
}
static __device__ __forceinline__ void st_rlx(unsigned long long* p, unsigned long long v) {
    asm volatile("st.relaxed.gpu.global.b64 [%0], %1;" :: "l"(p), "l"(v) : "memory");
}

__global__ void __launch_bounds__(NTHREADS, 1)
som_kernel(const float* __restrict__ X, const float* __restrict__ W0,
           const int* __restrict__ ep, float* __restrict__ out, int n_samples)
{
    const int cta  = blockIdx.x;
    const int tid  = threadIdx.x;
    const int warp = tid >> 5;
    const int lane = tid & 31;

    int epochs = *ep;
    if (epochs < 1 || epochs > 8) epochs = 1;
    const int TS = epochs * n_samples;           // <= 65536, tags fit 22 bits

    __shared__ float c_table[63 * 63];           // 0.1*exp(-0.5*sqrt(dx^2+dy^2))
    __shared__ float4 sm_ABV[2][NPC];            // (A, -2B, V), parity-buffered
    __shared__ float sm_c[2][NPC];               // per-neuron c, parity-buffered
    __shared__ unsigned long long sm_pack[NPC];  // prologue only

    for (int i = tid; i < 63 * 63; i += NTHREADS) {
        float dx = (float)(i / 63 - 31);
        float dy = (float)(i % 63 - 31);
        c_table[i] = 0.1f * expf(-0.5f * sqrtf(dx * dx + dy * dy));
    }
    if (tid < NPC) sm_c[1][tid] = 0.f;           // c(-1) = 0 for iteration 0

    // ---- neuron-warp state ----
    const int n = cta * NPC + warp;              // valid for warp < 16
    float w[KREG], v[KREG], u[KREG], xn[KREG];
    int pf = (n_samples > 2) ? 2 : (2 % n_samples);

    if (warp < NPC) {
        float a0 = 0.f, a1 = 0.f, a2 = 0.f, a3 = 0.f;
#pragma unroll
        for (int k = 0; k < KREG; k++) {
            float wk = W0[n * DIM + lane + 32 * k];
            w[k] = wk;
            v[k] = 0.f;
            float t0 = X[lane + 32 * k] - wk;    // u = x0 - w0
            u[k] = t0;
            if ((k & 3) == 0) a0 = fmaf(t0, t0, a0);
            else if ((k & 3) == 1) a1 = fmaf(t0, t0, a1);
            else if ((k & 3) == 2) a2 = fmaf(t0, t0, a2);
            else a3 = fmaf(t0, t0, a3);
        }
        float d2 = (a0 + a1) + (a2 + a3);
#pragma unroll
        for (int off = 16; off; off >>= 1)
            d2 += __shfl_xor_sync(0xFFFFFFFFu, d2, off);
#pragma unroll
        for (int k = 0; k < KREG; k++) xn[k] = X[DIM + lane + 32 * k];   // x1

        if (lane == 0)
            sm_pack[warp] = ((unsigned long long)__float_as_uint(d2) << 32)
                          | ((1u << 10) | (unsigned)n);
    }

    __syncthreads();                             // packs + sm_c[1] + LUT visible

    if (warp == NPC) {                           // store candidate(0), tag 1
        unsigned long long p = (lane < NPC) ? sm_pack[lane] : 0xFFFFFFFFFFFFFFFFull;
        unsigned phi = (unsigned)(p >> 32), plo = (unsigned)p;
        unsigned mhi = __reduce_min_sync(0xFFFFFFFFu, phi);
        unsigned cnd = (phi == mhi) ? plo : 0xFFFFFFFFu;
        unsigned mlo = __reduce_min_sync(0xFFFFFFFFu, cnd);
        if (lane == 0)
            st_rlx(&g_slots[0][cta * SLOT_STRIDE],
                   ((unsigned long long)mhi << 32) | mlo);
    }

    float ci = 0.f;                              // comm-lane c (persists across sync)
    const int nl = cta * NPC + (lane & 15);      // comm-lane neuron id (in range)
    const int lut_base = (nl >> 5) * 63 + (nl & 31) + (31 * 63 + 31);

    for (int t = 0; t < TS; ++t) {
        const int par = t & 1;

        if (warp == NPC) {
            // ======== comm: pipelined poll for bmu(t) ========
            const unsigned tag = (unsigned)(t + 1) & 0x3FFFFFu;
            const int ring = t & (RING - 1);
            unsigned long long* p0 = &g_slots[ring][lane * SLOT_STRIDE];
            unsigned long long* p1 = &g_slots[ring][(lane + 32) * SLOT_STRIDE];
            unsigned long long v0, v1;
            for (;;) {
                unsigned long long a0 = ld_rlx(p0), a1 = ld_rlx(p1);
                unsigned long long b0 = ld_rlx(p0), b1 = ld_rlx(p1);  // 2nd pair in flight
                bool oka = ((((unsigned)a0) >> 10) == tag) &&
                           ((((unsigned)a1) >> 10) == tag);
                if (__all_sync(0xFFFFFFFFu, oka)) { v0 = a0; v1 = a1; break; }
                bool okb = ((((unsigned)b0) >> 10) == tag) &&
                           ((((unsigned)b1) >> 10) == tag);
                if (__all_sync(0xFFFFFFFFu, okb)) { v0 = b0; v1 = b1; break; }
            }
            unsigned long long vm = (v0 < v1) ? v0 : v1;
            unsigned qhi = (unsigned)(vm >> 32), qlo = (unsigned)vm;
            unsigned gh = __reduce_min_sync(0xFFFFFFFFu, qhi);
            unsigned gc = (qhi == gh) ? qlo : 0xFFFFFFFFu;
            unsigned gl = __reduce_min_sync(0xFFFFFFFFu, gc);
            const int bmu = (int)(gl & 0x3FFu);

            ci = c_table[lut_base - (bmu >> 5) * 63 - (bmu & 31)];
            if (lane < NPC) sm_c[par][lane] = ci;    // consumed at iter t+1
        } else {
            // ======== neurons: window work (poll shadow) ========
            const float cp = sm_c[par ^ 1][warp];    // c(t-1), written iter t-1
#pragma unroll
            for (int k = 0; k < KREG; k++) {
                float vo = v[k];
                w[k] = fmaf(cp, vo, w[k]);
                v[k] = fmaf(-cp, vo, u[k]);
                u[k] = xn[k] - w[k];
            }
            const float* xp = X + (size_t)pf * DIM + lane;   // prefetch x(t+2)
#pragma unroll
            for (int k = 0; k < KREG; k++) xn[k] = xp[32 * k];
            pf++; if (pf == n_samples) pf = 0;

            float a0 = 0.f, a1 = 0.f, b0 = 0.f, b1 = 0.f, q0 = 0.f, q1 = 0.f;
#pragma unroll
            for (int k = 0; k < KREG; k += 2) {
                a0 = fmaf(u[k + 0], u[k + 0], a0); b0 = fmaf(u[k + 0], v[k + 0], b0);
                q0 = fmaf(v[k + 0], v[k + 0], q0);
                a1 = fmaf(u[k + 1], u[k + 1], a1); b1 = fmaf(u[k + 1], v[k + 1], b1);
                q1 = fmaf(v[k + 1], v[k + 1], q1);
            }
            float A = a0 + a1, B = b0 + b1, V = q0 + q1;
#pragma unroll
            for (int off = 16; off; off >>= 1) {
                A += __shfl_xor_sync(0xFFFFFFFFu, A, off);
                B += __shfl_xor_sync(0xFFFFFFFFu, B, off);
                V += __shfl_xor_sync(0xFFFFFFFFu, V, off);
            }
            if (lane == 0)
                sm_ABV[par][warp] = make_float4(A, -2.f * B, V, 0.f);
        }

        __syncthreads();   // joins: bmu/c(t) + ABV(t) visible (neurons arrived early)

        if (warp == NPC && t + 1 < TS) {
            // ======== comm tail: d2(t+1), CTA argmin, publish ========
            float4 q = sm_ABV[par][lane & 15];          // (A, -2B, V)
            float d2 = fmaxf(fmaf(ci, fmaf(ci, q.z, q.y), q.x), 0.f);
            unsigned tag2 = (unsigned)(t + 2) & 0x3FFFFFu;
            unsigned long long pk = (lane < NPC)
                ? (((unsigned long long)__float_as_uint(d2) << 32)
                   | ((tag2 << 10) | (unsigned)nl))
                : 0xFFFFFFFFFFFFFFFFull;
            unsigned phi = (unsigned)(pk >> 32), plo = (unsigned)pk;
            unsigned mhi = __reduce_min_sync(0xFFFFFFFFu, phi);
            unsigned cnd = (phi == mhi) ? plo : 0xFFFFFFFFu;
            unsigned mlo = __reduce_min_sync(0xFFFFFFFFu, cnd);
            if (lane == 0)
                st_rlx(&g_slots[(t + 1) & (RING - 1)][cta * SLOT_STRIDE],
                       ((unsigned long long)mhi << 32) | mlo);
        }
    }

    if (warp < NPC) {
        // epilogue: apply final update c(TS-1), write weights
        const float cp = sm_c[(TS - 1) & 1][warp];
#pragma unroll
        for (int k = 0; k < KREG; k++)
            out[n * DIM + lane + 32 * k] = fmaf(cp, v[k], w[k]);
    } else {
        // ---- termination handshake + scratch cleanup (deterministic replays) ----
        // ring(TS&3) received no candidate store (skipped at t=TS-1), so the
        // handshake tag TS+1 is this slot's unique terminal value.
        const unsigned ftag = (unsigned)(TS + 1) & 0x3FFFFFu;
        const int fring = TS & (RING - 1);
        if (lane == 0)
            st_rlx(&g_slots[fring][cta * SLOT_STRIDE],
                   (unsigned long long)(ftag << 10));

        if (cta == 0) {
            for (;;) {
                unsigned long long v0 = ld_rlx(&g_slots[fring][lane * SLOT_STRIDE]);
                unsigned long long v1 = ld_rlx(&g_slots[fring][(lane + 32) * SLOT_STRIDE]);
                bool ok = ((((unsigned)v0) >> 10) == ftag) &&
                          ((((unsigned)v1) >> 10) == ftag);
                if (__all_sync(0xFFFFFFFFu, ok)) break;
            }
#pragma unroll
            for (int r = 0; r < RING; r++) {
                st_rlx(&g_slots[r][lane * SLOT_STRIDE], 0ull);
                st_rlx(&g_slots[r][(lane + 32) * SLOT_STRIDE], 0ull);
            }
            __threadfence();
        }
    }
}

extern "C" void kernel_launch(void* const* d_in, const int* in_sizes, int n_in,
                              void* d_out, int out_size)
{
    const float* X  = (const float*)d_in[0];   // [8192, 384]
    const float* W0 = (const float*)d_in[1];   // [32, 32, 384]
    const int*   ep = (const int*)d_in[3];     // num_epochs
    float* out = (float*)d_out;                // [32, 32, 384]

    int n_samples = in_sizes[0] / DIM;
    som_kernel<<<NCTA, NTHREADS>>>(X, W0, ep, out, n_samples);
}